// round 3
// baseline (speedup 1.0000x reference)
#include <cuda_runtime.h>
#include <math.h>
#include <stdint.h>

// Problem constants
#define B_    8
#define C_    320
#define N_    4096     // H*W
#define SKV_  77
#define DKV_  1024
#define HEADS_ 8
#define DH_   64
#define INNER_ 512
#define MKV_  (B_ * SKV_)   // 616

// Scratch (allocation-free rule: __device__ globals)
__device__ float g_QpT[(size_t)B_ * INNER_ * N_];  // [b][inner][n]
__device__ float g_OT [(size_t)B_ * INNER_ * N_];  // [b][inner][n]
__device__ float g_Kp [(size_t)B_ * SKV_ * INNER_]; // pre-scaled by 1/8
__device__ float g_Vp [(size_t)B_ * SKV_ * INNER_];

// ---------------------------------------------------------------------------
// KV projection: [616,1024] @ [1024,512] -> Kp (scaled) / Vp.  z=0 -> K, z=1 -> V
// Tile 64x64x16, 256 threads, 4x4 per thread.
// ---------------------------------------------------------------------------
__global__ __launch_bounds__(256) void kv_proj_kernel(
    const float* __restrict__ kv,
    const float* __restrict__ Wk,
    const float* __restrict__ Wv)
{
    const bool isK = (blockIdx.z == 0);
    const float* __restrict__ W = isK ? Wk : Wv;
    float* __restrict__ Cout = isK ? g_Kp : g_Vp;
    const float scale = isK ? 0.125f : 1.0f;   // DIM_HEAD^-0.5 folded into K

    __shared__ float As[16][64];
    __shared__ float Bs[16][64];

    const int tid = threadIdx.x;
    const int mBase = blockIdx.x * 64;
    const int nBase = blockIdx.y * 64;
    const int rm = tid & 15;        // m lane
    const int cn = tid >> 4;        // n lane (0..15)

    float acc[4][4] = {};

    const int aRow  = tid >> 2;          // 0..63
    const int aCol4 = (tid & 3) * 4;     // 0,4,8,12
    const int bRow  = tid >> 4;          // 0..15
    const int bCol4 = (tid & 15) * 4;
    const int gm = mBase + aRow;

    for (int k0 = 0; k0 < DKV_; k0 += 16) {
        float4 av = make_float4(0.f, 0.f, 0.f, 0.f);
        if (gm < MKV_)
            av = *(const float4*)(kv + (size_t)gm * DKV_ + k0 + aCol4);
        As[aCol4 + 0][aRow] = av.x;
        As[aCol4 + 1][aRow] = av.y;
        As[aCol4 + 2][aRow] = av.z;
        As[aCol4 + 3][aRow] = av.w;
        *(float4*)&Bs[bRow][bCol4] =
            *(const float4*)(W + (size_t)(k0 + bRow) * INNER_ + nBase + bCol4);
        __syncthreads();
        #pragma unroll
        for (int kk = 0; kk < 16; ++kk) {
            float a[4], bv[4];
            #pragma unroll
            for (int i = 0; i < 4; ++i) a[i]  = As[kk][rm + 16 * i];
            #pragma unroll
            for (int j = 0; j < 4; ++j) bv[j] = Bs[kk][cn + 16 * j];
            #pragma unroll
            for (int i = 0; i < 4; ++i)
                #pragma unroll
                for (int j = 0; j < 4; ++j)
                    acc[i][j] += a[i] * bv[j];
        }
        __syncthreads();
    }
    #pragma unroll
    for (int i = 0; i < 4; ++i) {
        const int m = mBase + rm + 16 * i;
        if (m < MKV_) {
            #pragma unroll
            for (int j = 0; j < 4; ++j)
                Cout[(size_t)m * INNER_ + nBase + cn + 16 * j] = acc[i][j] * scale;
        }
    }
}

// ---------------------------------------------------------------------------
// Q projection: per batch, A col-major (query is [C][N], n contiguous),
// [4096,320] @ [320,512] -> QpT[b][inner][n] (transposed store, coalesced).
// Tile 128x64x16, 256 threads, 8x4 per thread.
// ---------------------------------------------------------------------------
__global__ __launch_bounds__(256) void q_proj_kernel(
    const float* __restrict__ query,
    const float* __restrict__ Wq)
{
    const int b = blockIdx.z;
    const int mBase = blockIdx.x * 128;
    const int nBase = blockIdx.y * 64;

    __shared__ float As[16][128];
    __shared__ float Bs[16][64];

    const int tid = threadIdx.x;
    const int rm = tid & 15;
    const int cn = tid >> 4;
    float acc[8][4] = {};

    const float* __restrict__ A = query + (size_t)b * C_ * N_;  // A[m,k]=A[k*N_+m]
    const int kcol = tid >> 4;       // 0..15
    const int mo   = tid & 15;       // 0..15
    const int bRow = tid >> 4, bCol4 = (tid & 15) * 4;

    for (int k0 = 0; k0 < C_; k0 += 16) {
        #pragma unroll
        for (int r = 0; r < 2; ++r) {
            const int m4 = (mo + 16 * r) * 4;    // 0..124
            *(float4*)&As[kcol][m4] =
                *(const float4*)(A + (size_t)(k0 + kcol) * N_ + mBase + m4);
        }
        *(float4*)&Bs[bRow][bCol4] =
            *(const float4*)(Wq + (size_t)(k0 + bRow) * INNER_ + nBase + bCol4);
        __syncthreads();
        #pragma unroll
        for (int kk = 0; kk < 16; ++kk) {
            float a[8], bv[4];
            #pragma unroll
            for (int i = 0; i < 8; ++i) a[i]  = As[kk][rm + 16 * i];
            #pragma unroll
            for (int j = 0; j < 4; ++j) bv[j] = Bs[kk][cn + 16 * j];
            #pragma unroll
            for (int i = 0; i < 8; ++i)
                #pragma unroll
                for (int j = 0; j < 4; ++j)
                    acc[i][j] += a[i] * bv[j];
        }
        __syncthreads();
    }
    float* __restrict__ Cp = g_QpT + (size_t)b * INNER_ * N_;
    #pragma unroll
    for (int j = 0; j < 4; ++j)
        #pragma unroll
        for (int i = 0; i < 8; ++i)
            Cp[(size_t)(nBase + cn + 16 * j) * N_ + mBase + rm + 16 * i] = acc[i][j];
}

// ---------------------------------------------------------------------------
// Attention: one thread per query row. K (pre-scaled) then V staged through
// the same smem buffer; logits in smem [77][128] (bank-per-thread).
// ---------------------------------------------------------------------------
#define ATTN_SMEM_BYTES ((SKV_ * DH_ + SKV_ * 128) * (int)sizeof(float))  // 59136

__global__ __launch_bounds__(128) void attn_kernel()
{
    extern __shared__ float sm[];
    float* __restrict__ KV = sm;                 // 77*64
    float* __restrict__ L  = sm + SKV_ * DH_;    // [77][128]

    const int b = blockIdx.z;
    const int h = blockIdx.y;
    const int tid = threadIdx.x;
    const int n = blockIdx.x * 128 + tid;

    // q row -> registers (coalesced: consecutive threads, consecutive n)
    float q[DH_];
    const float* __restrict__ qp = g_QpT + (size_t)b * INNER_ * N_ + (size_t)h * DH_ * N_ + n;
    #pragma unroll
    for (int d = 0; d < DH_; ++d) q[d] = qp[(size_t)d * N_];

    // stage K (scaled)
    {
        const float* __restrict__ kp = g_Kp + (size_t)b * SKV_ * INNER_ + h * DH_;
        for (int i4 = tid; i4 < SKV_ * DH_ / 4; i4 += 128) {
            const int s = i4 >> 4, d4 = (i4 & 15) << 2;
            *(float4*)(KV + (i4 << 2)) = *(const float4*)(kp + (size_t)s * INNER_ + d4);
        }
    }
    __syncthreads();

    // logits + max
    float maxv = -1e30f;
    for (int s = 0; s < SKV_; ++s) {
        float dot = 0.f;
        #pragma unroll
        for (int d4 = 0; d4 < DH_ / 4; ++d4) {
            const float4 k4 = *(const float4*)(KV + s * DH_ + d4 * 4);
            dot += q[4 * d4 + 0] * k4.x;
            dot += q[4 * d4 + 1] * k4.y;
            dot += q[4 * d4 + 2] * k4.z;
            dot += q[4 * d4 + 3] * k4.w;
        }
        L[s * 128 + tid] = dot;
        maxv = fmaxf(maxv, dot);
    }

    // softmax numerator + sum
    float sum = 0.f;
    for (int s = 0; s < SKV_; ++s) {
        const float e = __expf(L[s * 128 + tid] - maxv);
        L[s * 128 + tid] = e;
        sum += e;
    }
    const float inv = 1.f / sum;

    __syncthreads();  // everyone done reading K before V overwrites buffer

    // stage V
    {
        const float* __restrict__ vp = g_Vp + (size_t)b * SKV_ * INNER_ + h * DH_;
        for (int i4 = tid; i4 < SKV_ * DH_ / 4; i4 += 128) {
            const int s = i4 >> 4, d4 = (i4 & 15) << 2;
            *(float4*)(KV + (i4 << 2)) = *(const float4*)(vp + (size_t)s * INNER_ + d4);
        }
    }
    __syncthreads();

    // AV
    float acc[DH_] = {};
    for (int s = 0; s < SKV_; ++s) {
        const float p = L[s * 128 + tid];
        #pragma unroll
        for (int d4 = 0; d4 < DH_ / 4; ++d4) {
            const float4 v4 = *(const float4*)(KV + s * DH_ + d4 * 4);
            acc[4 * d4 + 0] += p * v4.x;
            acc[4 * d4 + 1] += p * v4.y;
            acc[4 * d4 + 2] += p * v4.z;
            acc[4 * d4 + 3] += p * v4.w;
        }
    }

    // store O transposed (coalesced)
    float* __restrict__ op = g_OT + (size_t)b * INNER_ * N_ + (size_t)h * DH_ * N_ + n;
    #pragma unroll
    for (int d = 0; d < DH_; ++d) op[(size_t)d * N_] = acc[d] * inv;
}

// ---------------------------------------------------------------------------
// Output projection: per batch, A = OT (col-major view, n contiguous),
// [4096,512] @ [512,320] + bo -> out[b][c][n] (transposed store == NCHW!)
// Tile 128x64x16, 256 threads, 8x4 per thread.
// ---------------------------------------------------------------------------
__global__ __launch_bounds__(256) void out_proj_kernel(
    const float* __restrict__ Wo,
    const float* __restrict__ bo,
    float* __restrict__ out)
{
    const int b = blockIdx.z;
    const int mBase = blockIdx.x * 128;
    const int nBase = blockIdx.y * 64;

    __shared__ float As[16][128];
    __shared__ float Bs[16][64];

    const int tid = threadIdx.x;
    const int rm = tid & 15;
    const int cn = tid >> 4;
    float acc[8][4] = {};

    const float* __restrict__ A = g_OT + (size_t)b * INNER_ * N_;
    const int kcol = tid >> 4;
    const int mo   = tid & 15;
    const int bRow = tid >> 4, bCol4 = (tid & 15) * 4;

    for (int k0 = 0; k0 < INNER_; k0 += 16) {
        #pragma unroll
        for (int r = 0; r < 2; ++r) {
            const int m4 = (mo + 16 * r) * 4;
            *(float4*)&As[kcol][m4] =
                *(const float4*)(A + (size_t)(k0 + kcol) * N_ + mBase + m4);
        }
        *(float4*)&Bs[bRow][bCol4] =
            *(const float4*)(Wo + (size_t)(k0 + bRow) * C_ + nBase + bCol4);
        __syncthreads();
        #pragma unroll
        for (int kk = 0; kk < 16; ++kk) {
            float a[8], bv[4];
            #pragma unroll
            for (int i = 0; i < 8; ++i) a[i]  = As[kk][rm + 16 * i];
            #pragma unroll
            for (int j = 0; j < 4; ++j) bv[j] = Bs[kk][cn + 16 * j];
            #pragma unroll
            for (int i = 0; i < 8; ++i)
                #pragma unroll
                for (int j = 0; j < 4; ++j)
                    acc[i][j] += a[i] * bv[j];
        }
        __syncthreads();
    }
    float* __restrict__ op = out + (size_t)b * C_ * N_;
    #pragma unroll
    for (int j = 0; j < 4; ++j) {
        const float bias = bo[nBase + cn + 16 * j];
        #pragma unroll
        for (int i = 0; i < 8; ++i)
            op[(size_t)(nBase + cn + 16 * j) * N_ + mBase + rm + 16 * i] =
                acc[i][j] + bias;
    }
}

// ---------------------------------------------------------------------------
extern "C" void kernel_launch(void* const* d_in, const int* in_sizes, int n_in,
                              void* d_out, int out_size)
{
    const float* query = (const float*)d_in[0];  // [B,C,H,W]
    const float* kv    = (const float*)d_in[1];  // [B,S,DKV]
    const float* Wq    = (const float*)d_in[2];  // [C,INNER]
    const float* Wk    = (const float*)d_in[3];  // [DKV,INNER]
    const float* Wv    = (const float*)d_in[4];  // [DKV,INNER]
    const float* Wo    = (const float*)d_in[5];  // [INNER,C]
    const float* bo    = (const float*)d_in[6];  // [C]
    float* out = (float*)d_out;

    // opt in to >48KB dynamic smem for attention (idempotent, capture-safe)
    cudaFuncSetAttribute(attn_kernel,
                         cudaFuncAttributeMaxDynamicSharedMemorySize,
                         ATTN_SMEM_BYTES);

    {   // K & V projections (independent of Q path)
        dim3 grid((MKV_ + 63) / 64, INNER_ / 64, 2);   // 10 x 8 x 2
        kv_proj_kernel<<<grid, 256>>>(kv, Wk, Wv);
    }
    {   // Q projection
        dim3 grid(N_ / 128, INNER_ / 64, B_);          // 32 x 8 x 8
        q_proj_kernel<<<grid, 256>>>(query, Wq);
    }
    {   // attention
        dim3 grid(N_ / 128, HEADS_, B_);               // 32 x 8 x 8
        attn_kernel<<<grid, 128, ATTN_SMEM_BYTES>>>();
    }
    {   // output projection + bias + NCHW store
        dim3 grid(N_ / 128, C_ / 64, B_);              // 32 x 5 x 8
        out_proj_kernel<<<grid, 256>>>(Wo, bo, out);
    }
}